// round 13
// baseline (speedup 1.0000x reference)
#include <cuda_runtime.h>
#include <math.h>

// ---------------- composed-weight shared layout ----------------
//  W3X [68][12] : 0   .. 816  (rows uv*4+t for uv<16; rows 64..67 = G2[t]; pads ZEROED)
//  QX  [17]     : 816 .. 833  (QX[16] = q0)
//  A1  [4][5]   : 836 .. 856
//  B1  [4][5]   : 856 .. 876
//  c5  [5]      : 876 .. 881
//  H   [5][12]  : 884 .. 944  (pads ZEROED)
//  Cm  [5][4]   : 944 .. 964
//  r5  [5]      : 964 .. 969
#define W3X_OFF 0
#define QX_OFF  816
#define A1_OFF  836
#define B1_OFF  856
#define C5_OFF  876
#define H_OFF   884
#define CM_OFF  944
#define R5_OFF  964
#define PREP_SIZE 976

// ---------------- f32x2 helpers ----------------
typedef unsigned long long u64;

__device__ __forceinline__ u64 pack2(float x, float y) {
    u64 r; asm("mov.b64 %0, {%1, %2};" : "=l"(r) : "f"(x), "f"(y)); return r;
}
__device__ __forceinline__ u64 mul2(u64 a, u64 b) {
    u64 r; asm("mul.rn.f32x2 %0, %1, %2;" : "=l"(r) : "l"(a), "l"(b)); return r;
}
__device__ __forceinline__ void fma2(u64 &d, u64 a, u64 b) {
    asm("fma.rn.f32x2 %0, %1, %2, %0;" : "+l"(d) : "l"(a), "l"(b));
}
__device__ __forceinline__ float2 unpk(u64 v) {
    float2 r; asm("mov.b64 {%0, %1}, %2;" : "=f"(r.x), "=f"(r.y) : "l"(v)); return r;
}

// ---------------- persistent fused kernel: prep once/block + grid-stride rows ----------------
__global__ __launch_bounds__(128, 4)
void dock_kernel(const float* __restrict__ lig, const float* __restrict__ rec,
                 float* __restrict__ out, int B,
                 const float* __restrict__ w1_000, const float* __restrict__ w1_110,
                 const float* __restrict__ w1_011, const float* __restrict__ w1_101,
                 const float* __restrict__ w1_111, const float* __restrict__ w2_000,
                 const float* __restrict__ w2_110, const float* __restrict__ w2_011,
                 const float* __restrict__ w2_101, const float* __restrict__ w2_111)
{
    const float C1_000 = 0.24253562503633297f;   // sqrt(1/17)
    const float C1_110 = 0.14002800840280097f;   // sqrt(1/17)/sqrt(3)
    const float C1_011 = 0.3333333333333333f;    // sqrt(3/9)/sqrt(3)
    const float C1_101 = C1_011;
    const float C1_111 = 0.23570226039551587f;   // sqrt(3/9)/sqrt(6)
    const float C2_000 = 0.10846522890932808f;   // sqrt(1/85)
    const float C2_110 = 0.06262242910851495f;   // sqrt(1/85)/sqrt(3)
    const float C2_011 = 0.14907119849998599f;   // sqrt(3/45)/sqrt(3)
    const float C2_101 = C2_011;
    const float C2_111 = 0.10540925533894598f;   // sqrt(3/45)/sqrt(6)

    __shared__ __align__(16) float sw[PREP_SIZE];
    __shared__ float sm1[320];   // w1_000
    __shared__ float sm2[720];   // w2_000
    __shared__ float smv[40];    // [0:20) w1_110, [20:40) w2_011

    const int tid = threadIdx.x;

    // ---- one-time per-block prep (592 blocks = 1 wave; paid once) ----
    #pragma unroll
    for (int j = tid; j < PREP_SIZE; j += 128) sw[j] = 0.f;
    #pragma unroll
    for (int j = tid; j < 320; j += 128) sm1[j] = w1_000[j];
    #pragma unroll
    for (int j = tid; j < 720; j += 128) sm2[j] = w2_000[j];
    if (tid < 20)       smv[tid] = w1_110[tid];
    else if (tid < 40)  smv[tid] = w2_011[tid - 20];
    __syncthreads();

    // 629 "20-contraction" outputs split over 128 threads (5 iters max)
    for (int j = tid; j < 629; j += 128) {
        if (j < 576) {
            int w = j % 9, t = (j / 9) & 3, uvi = j / 36;
            float s = 0.f;
            #pragma unroll
            for (int m = 0; m < 20; m++) s += sm1[uvi*20 + m] * sm2[(m*4 + t)*9 + w];
            sw[W3X_OFF + (uvi*4 + t)*12 + w] = C2_000 * C1_000 * s;
        } else if (j < 612) {
            int k = j - 576, w = k % 9, t = k / 9;
            float s = 0.f;
            #pragma unroll
            for (int m = 0; m < 20; m++) s += smv[m] * sm2[(m*4 + t)*9 + w];
            sw[W3X_OFF + (64 + t)*12 + w] = C2_000 * C1_110 * s;   // G2 as uv=16 rows
        } else if (j < 628) {
            int uvi = j - 612;
            float s = 0.f;
            #pragma unroll
            for (int m = 0; m < 20; m++) s += sm1[uvi*20 + m] * smv[20 + m];
            sw[QX_OFF + uvi] = C2_011 * C1_000 * s;
        } else {
            float s = 0.f;
            #pragma unroll
            for (int m = 0; m < 20; m++) s += smv[m] * smv[20 + m];
            sw[QX_OFF + 16] = C2_011 * C1_110 * s;                 // q0 as QX[16]
        }
    }
    // small tables
    if (tid < 20) sw[A1_OFF + tid] = C1_011 * w1_011[tid];
    if (tid < 20) sw[B1_OFF + tid] = C1_101 * w1_101[tid];
    if (tid < 5)  sw[C5_OFF + tid] = C1_111 * w1_111[tid];
    if (tid < 45) { int u = tid/9, w = tid%9; sw[H_OFF + u*12 + w] = C2_110 * w2_110[tid]; }
    if (tid < 20) sw[CM_OFF + tid] = C2_101 * w2_101[tid];
    if (tid < 5)  sw[R5_OFF + tid] = C2_111 * w2_111[tid];
    __syncthreads();

    // ---- persistent grid-stride loop over row-pairs ----
    const float COEFF = -0.18f;                    // -0.5/(5/3)^2
    const float OF1 = 5.f/3.f, OF2 = 10.f/3.f, OF3 = 5.f;

    const int npairs = (B + 1) >> 1;
    const int T = gridDim.x * 128;

    for (int i = blockIdx.x * 128 + tid; i < npairs; i += T) {
        int r0 = 2 * i;
        bool two = (r0 + 1 < B);

        float sA[2][3][4], vA[2][3][3];
        #pragma unroll
        for (int r = 0; r < 2; r++) {
            int row = (two && r) ? (r0 + 1) : r0;
            const float4* L = reinterpret_cast<const float4*>(lig) + (size_t)row*3;
            const float4* R = reinterpret_cast<const float4*>(rec) + (size_t)row*3;
            float4 l0=L[0], l1=L[1], l2=L[2];
            float4 q0=R[0], q1=R[1], q2=R[2];
            float ev[9];
            ev[0]=l0.w-q0.w; ev[1]=l1.x-q1.x; ev[2]=l1.y-q1.y;
            ev[3]=l1.z-q1.z; ev[4]=l1.w-q1.w; ev[5]=l2.x-q2.x;
            ev[6]=l2.y-q2.y; ev[7]=l2.z-q2.z; ev[8]=l2.w-q2.w;
            #pragma unroll
            for (int e = 0; e < 3; e++) {
                float ex=ev[3*e], ey=ev[3*e+1], ez=ev[3*e+2];
                float d2 = ex*ex + ey*ey + ez*ez;
                float rs = rsqrtf(d2); float d = d2*rs;
                vA[r][e][0]=ex*rs; vA[r][e][1]=ey*rs; vA[r][e][2]=ez*rs;
                float t1=d-OF1, t2=d-OF2, t3=d-OF3;
                sA[r][e][0]=__expf(COEFF*d*d);
                sA[r][e][1]=__expf(COEFF*t1*t1);
                sA[r][e][2]=__expf(COEFF*t2*t2);
                sA[r][e][3]=__expf(COEFF*t3*t3);
            }
        }

        float dot12[2], cr[2][3];
        u64 s3p[2][4];
        #pragma unroll
        for (int r = 0; r < 2; r++) {
            dot12[r] = vA[r][0][0]*vA[r][1][0] + vA[r][0][1]*vA[r][1][1] + vA[r][0][2]*vA[r][1][2];
            cr[r][0] = vA[r][0][1]*vA[r][1][2] - vA[r][0][2]*vA[r][1][1];
            cr[r][1] = vA[r][0][2]*vA[r][1][0] - vA[r][0][0]*vA[r][1][2];
            cr[r][2] = vA[r][0][0]*vA[r][1][1] - vA[r][0][1]*vA[r][1][0];
            #pragma unroll
            for (int t = 0; t < 4; t++) s3p[r][t] = pack2(sA[r][2][t], sA[r][2][t]);
        }

        u64 accp[2][5];
        #pragma unroll
        for (int r = 0; r < 2; r++)
            #pragma unroll
            for (int k = 0; k < 5; k++) accp[r][k] = 0ull;

        float scal[2] = {0.f, 0.f};

        // Fused trilinear incl. G2-as-uv16 (both big einsums + dot12 term; S never materialized)
        #pragma unroll
        for (int uv = 0; uv < 17; uv++) {
            float q = sw[QX_OFF + uv];
            u64 pvp[2];
            #pragma unroll
            for (int r = 0; r < 2; r++) {
                float pv = (uv < 16) ? (sA[r][0][uv >> 2] * sA[r][1][uv & 3]) : dot12[r];
                scal[r] += q * pv;
                pvp[r] = pack2(pv, pv);
            }
            #pragma unroll
            for (int t = 0; t < 4; t++) {
                const float* wb = &sw[W3X_OFF + (uv*4 + t)*12];
                ulonglong2 p0 = *reinterpret_cast<const ulonglong2*>(wb);
                ulonglong2 p1 = *reinterpret_cast<const ulonglong2*>(wb + 4);
                u64 p2 = *reinterpret_cast<const u64*>(wb + 8);
                #pragma unroll
                for (int r = 0; r < 2; r++) {
                    u64 f2 = mul2(pvp[r], s3p[r][t]);
                    fma2(accp[r][0], p0.x, f2);
                    fma2(accp[r][1], p0.y, f2);
                    fma2(accp[r][2], p1.x, f2);
                    fma2(accp[r][3], p1.y, f2);
                    fma2(accp[r][4], p2,   f2);
                }
            }
        }

        // Single fused V loop: build V[w] transiently, consume into acc / t2 / wv
        float t2[2][3], wv[2][3];
        #pragma unroll
        for (int r = 0; r < 2; r++) {
            t2[r][0]=scal[r]*vA[r][2][0]; t2[r][1]=scal[r]*vA[r][2][1]; t2[r][2]=scal[r]*vA[r][2][2];
            wv[r][0]=0.f; wv[r][1]=0.f; wv[r][2]=0.f;
        }
        #pragma unroll
        for (int w = 0; w < 5; w++) {
            float a0=sw[A1_OFF+0*5+w], a1=sw[A1_OFF+1*5+w], a2=sw[A1_OFF+2*5+w], a3=sw[A1_OFF+3*5+w];
            float b0=sw[B1_OFF+0*5+w], b1=sw[B1_OFF+1*5+w], b2=sw[B1_OFF+2*5+w], b3=sw[B1_OFF+3*5+w];
            float cw = sw[C5_OFF + w];
            float c0=sw[CM_OFF+w*4+0], c1=sw[CM_OFF+w*4+1], c2=sw[CM_OFF+w*4+2], c3=sw[CM_OFF+w*4+3];
            float ru = sw[R5_OFF + w];
            const float* hb = &sw[H_OFF + w*12];
            ulonglong2 h0 = *reinterpret_cast<const ulonglong2*>(hb);
            ulonglong2 h1 = *reinterpret_cast<const ulonglong2*>(hb + 4);
            u64 h2 = *reinterpret_cast<const u64*>(hb + 8);
            #pragma unroll
            for (int r = 0; r < 2; r++) {
                float aw = a0*sA[r][0][0] + a1*sA[r][0][1] + a2*sA[r][0][2] + a3*sA[r][0][3];
                float bw = b0*sA[r][1][0] + b1*sA[r][1][1] + b2*sA[r][1][2] + b3*sA[r][1][3];
                float Vx = aw*vA[r][1][0] + bw*vA[r][0][0] + cw*cr[r][0];
                float Vy = aw*vA[r][1][1] + bw*vA[r][0][1] + cw*cr[r][1];
                float Vz = aw*vA[r][1][2] + bw*vA[r][0][2] + cw*cr[r][2];
                // H-term
                float vd = Vx*vA[r][2][0] + Vy*vA[r][2][1] + Vz*vA[r][2][2];
                u64 vd2 = pack2(vd, vd);
                fma2(accp[r][0], h0.x, vd2);
                fma2(accp[r][1], h0.y, vd2);
                fma2(accp[r][2], h1.x, vd2);
                fma2(accp[r][3], h1.y, vd2);
                fma2(accp[r][4], h2,   vd2);
                // Cm / r5 terms
                float cu = c0*sA[r][2][0] + c1*sA[r][2][1] + c2*sA[r][2][2] + c3*sA[r][2][3];
                t2[r][0] += cu*Vx; t2[r][1] += cu*Vy; t2[r][2] += cu*Vz;
                wv[r][0] += ru*Vx; wv[r][1] += ru*Vy; wv[r][2] += ru*Vz;
            }
        }

        // final cross into V2
        float v2o[2][3];
        #pragma unroll
        for (int r = 0; r < 2; r++) {
            v2o[r][0] = t2[r][0] + wv[r][1]*vA[r][2][2] - wv[r][2]*vA[r][2][1];
            v2o[r][1] = t2[r][1] + wv[r][2]*vA[r][2][0] - wv[r][0]*vA[r][2][2];
            v2o[r][2] = t2[r][2] + wv[r][0]*vA[r][2][1] - wv[r][1]*vA[r][2][0];
        }

        // stores: 4 concatenated [B,3] regions; unpack accumulators directly
        float2 a0r0 = unpk(accp[0][0]), a1r0 = unpk(accp[0][1]), a2r0 = unpk(accp[0][2]);
        float2 a3r0 = unpk(accp[0][3]), a4r0 = unpk(accp[0][4]);
        float2 a0r1 = unpk(accp[1][0]), a1r1 = unpk(accp[1][1]), a2r1 = unpk(accp[1][2]);
        float2 a3r1 = unpk(accp[1][3]), a4r1 = unpk(accp[1][4]);
        float val0[12] = { a0r0.x,a0r0.y,a1r0.x,a1r0.y,a2r0.x,a2r0.y,a3r0.x,a3r0.y,a4r0.x,
                           v2o[0][0],v2o[0][1],v2o[0][2] };
        float val1[12] = { a0r1.x,a0r1.y,a1r1.x,a1r1.y,a2r1.x,a2r1.y,a3r1.x,a3r1.y,a4r1.x,
                           v2o[1][0],v2o[1][1],v2o[1][2] };

        if (two && ((B & 1) == 0)) {
            #pragma unroll
            for (int g = 0; g < 4; g++) {
                float2* o = reinterpret_cast<float2*>(out + (size_t)(3*g)*B + (size_t)3*r0);
                o[0] = make_float2(val0[3*g+0], val0[3*g+1]);
                o[1] = make_float2(val0[3*g+2], val1[3*g+0]);
                o[2] = make_float2(val1[3*g+1], val1[3*g+2]);
            }
        } else {
            #pragma unroll
            for (int g = 0; g < 4; g++) {
                float* o = out + (size_t)(3*g)*B + (size_t)3*r0;
                o[0]=val0[3*g+0]; o[1]=val0[3*g+1]; o[2]=val0[3*g+2];
                if (two) { o[3]=val1[3*g+0]; o[4]=val1[3*g+1]; o[5]=val1[3*g+2]; }
            }
        }
    }
}

extern "C" void kernel_launch(void* const* d_in, const int* in_sizes, int n_in,
                              void* d_out, int out_size)
{
    const float* lig    = (const float*)d_in[0];
    const float* rec    = (const float*)d_in[1];
    const float* w1_000 = (const float*)d_in[2];
    const float* w1_110 = (const float*)d_in[3];
    const float* w1_011 = (const float*)d_in[4];
    const float* w1_101 = (const float*)d_in[5];
    const float* w1_111 = (const float*)d_in[6];
    const float* w2_000 = (const float*)d_in[7];
    const float* w2_110 = (const float*)d_in[8];
    const float* w2_011 = (const float*)d_in[9];
    const float* w2_101 = (const float*)d_in[10];
    const float* w2_111 = (const float*)d_in[11];

    int B = in_sizes[0] / 12;
    int npairs = (B + 1) / 2;
    int tiles = (npairs + 127) / 128;

    int dev = 0, sms = 148;
    cudaGetDevice(&dev);
    cudaDeviceGetAttribute(&sms, cudaDevAttrMultiProcessorCount, dev);
    int grid = sms * 4;                  // exactly one resident wave (4 blocks/SM)
    if (grid > tiles) grid = tiles;

    dock_kernel<<<grid, 128>>>(
        lig, rec, (float*)d_out, B,
        w1_000, w1_110, w1_011, w1_101, w1_111,
        w2_000, w2_110, w2_011, w2_101, w2_111);
}

// round 14
// speedup vs baseline: 1.0083x; 1.0083x over previous
#include <cuda_runtime.h>
#include <math.h>

// ---------------- composed-weight shared layout (R10 layout) ----------------
//  W3  [64][12] : 0    .. 768   (w padded 9->12, pads ZEROED)
//  G2  [4][12]  : 768  .. 816
//  Q   [4][4]   : 816  .. 832
//  q0           : 832
//  A1  [4][5]   : 836  .. 856
//  B1  [4][5]   : 856  .. 876
//  c5  [5]      : 876  .. 881
//  H   [5][12]  : 884  .. 944   (pads ZEROED)
//  Cm  [5][4]   : 944  .. 964
//  r5  [5]      : 964  .. 969
#define W3_OFF 0
#define G2_OFF 768
#define Q_OFF  816
#define Q0_OFF 832
#define A1_OFF 836
#define B1_OFF 856
#define C5_OFF 876
#define H_OFF  884
#define CM_OFF 944
#define R5_OFF 964
#define PREP_SIZE 976

// ---------------- f32x2 helpers ----------------
typedef unsigned long long u64;

__device__ __forceinline__ u64 pack2(float x, float y) {
    u64 r; asm("mov.b64 %0, {%1, %2};" : "=l"(r) : "f"(x), "f"(y)); return r;
}
__device__ __forceinline__ u64 mul2(u64 a, u64 b) {
    u64 r; asm("mul.rn.f32x2 %0, %1, %2;" : "=l"(r) : "l"(a), "l"(b)); return r;
}
__device__ __forceinline__ void fma2(u64 &d, u64 a, u64 b) {
    asm("fma.rn.f32x2 %0, %1, %2, %0;" : "+l"(d) : "l"(a), "l"(b));
}
__device__ __forceinline__ float2 unpk(u64 v) {
    float2 r; asm("mov.b64 {%0, %1}, %2;" : "=f"(r.x), "=f"(r.y) : "l"(v)); return r;
}

// ---------------- persistent fused kernel: prep once/block + chunked rows ----------------
__global__ __launch_bounds__(128, 4)
void dock_kernel(const float* __restrict__ lig, const float* __restrict__ rec,
                 float* __restrict__ out, int B,
                 const float* __restrict__ w1_000, const float* __restrict__ w1_110,
                 const float* __restrict__ w1_011, const float* __restrict__ w1_101,
                 const float* __restrict__ w1_111, const float* __restrict__ w2_000,
                 const float* __restrict__ w2_110, const float* __restrict__ w2_011,
                 const float* __restrict__ w2_101, const float* __restrict__ w2_111)
{
    const float C1_000 = 0.24253562503633297f;   // sqrt(1/17)
    const float C1_110 = 0.14002800840280097f;   // sqrt(1/17)/sqrt(3)
    const float C1_011 = 0.3333333333333333f;    // sqrt(3/9)/sqrt(3)
    const float C1_101 = C1_011;
    const float C1_111 = 0.23570226039551587f;   // sqrt(3/9)/sqrt(6)
    const float C2_000 = 0.10846522890932808f;   // sqrt(1/85)
    const float C2_110 = 0.06262242910851495f;   // sqrt(1/85)/sqrt(3)
    const float C2_011 = 0.14907119849998599f;   // sqrt(3/45)/sqrt(3)
    const float C2_101 = C2_011;
    const float C2_111 = 0.10540925533894598f;   // sqrt(3/45)/sqrt(6)

    __shared__ __align__(16) float sw[PREP_SIZE];
    __shared__ float sm1[320];   // w1_000
    __shared__ float sm2[720];   // w2_000
    __shared__ float smv[40];    // [0:20) w1_110, [20:40) w2_011

    const int tid = threadIdx.x;

    // ---- one-time per-block prep (one resident wave; paid once per block) ----
    #pragma unroll
    for (int j = tid; j < PREP_SIZE; j += 128) sw[j] = 0.f;
    #pragma unroll
    for (int j = tid; j < 320; j += 128) sm1[j] = w1_000[j];
    #pragma unroll
    for (int j = tid; j < 720; j += 128) sm2[j] = w2_000[j];
    if (tid < 20)       smv[tid] = w1_110[tid];
    else if (tid < 40)  smv[tid] = w2_011[tid - 20];
    __syncthreads();

    // 629 "20-contraction" outputs split over 128 threads (<=5 iters each)
    for (int j = tid; j < 629; j += 128) {
        if (j < 576) {
            int w = j % 9, t = (j / 9) & 3, uvi = j / 36;
            float s = 0.f;
            #pragma unroll
            for (int m = 0; m < 20; m++) s += sm1[uvi*20 + m] * sm2[(m*4 + t)*9 + w];
            sw[W3_OFF + (uvi*4 + t)*12 + w] = C2_000 * C1_000 * s;
        } else if (j < 612) {
            int k = j - 576, w = k % 9, t = k / 9;
            float s = 0.f;
            #pragma unroll
            for (int m = 0; m < 20; m++) s += smv[m] * sm2[(m*4 + t)*9 + w];
            sw[G2_OFF + t*12 + w] = C2_000 * C1_110 * s;
        } else if (j < 628) {
            int uvi = j - 612;
            float s = 0.f;
            #pragma unroll
            for (int m = 0; m < 20; m++) s += sm1[uvi*20 + m] * smv[20 + m];
            sw[Q_OFF + uvi] = C2_011 * C1_000 * s;
        } else {
            float s = 0.f;
            #pragma unroll
            for (int m = 0; m < 20; m++) s += smv[m] * smv[20 + m];
            sw[Q0_OFF] = C2_011 * C1_110 * s;
        }
    }
    // small tables
    if (tid < 20) sw[A1_OFF + tid] = C1_011 * w1_011[tid];
    if (tid < 20) sw[B1_OFF + tid] = C1_101 * w1_101[tid];
    if (tid < 5)  sw[C5_OFF + tid] = C1_111 * w1_111[tid];
    if (tid < 45) { int u = tid/9, w = tid%9; sw[H_OFF + u*12 + w] = C2_110 * w2_110[tid]; }
    if (tid < 20) sw[CM_OFF + tid] = C2_101 * w2_101[tid];
    if (tid < 5)  sw[R5_OFF + tid] = C2_111 * w2_111[tid];
    __syncthreads();

    // ---- chunked persistent loop over row-pairs (contiguous per block) ----
    const float COEFF = -0.18f;                    // -0.5/(5/3)^2
    const float OF1 = 5.f/3.f, OF2 = 10.f/3.f, OF3 = 5.f;

    const int npairs = (B + 1) >> 1;
    const int chunk  = (npairs + gridDim.x - 1) / gridDim.x;
    const int i_beg  = blockIdx.x * chunk;
    int i_end = i_beg + chunk; if (i_end > npairs) i_end = npairs;

    for (int i = i_beg + tid; i < i_end; i += 128) {
        int r0 = 2 * i;
        bool two = (r0 + 1 < B);

        float sA[2][3][4], vA[2][3][3];
        #pragma unroll
        for (int r = 0; r < 2; r++) {
            int row = (two && r) ? (r0 + 1) : r0;
            const float4* L = reinterpret_cast<const float4*>(lig) + (size_t)row*3;
            const float4* R = reinterpret_cast<const float4*>(rec) + (size_t)row*3;
            float4 l0=L[0], l1=L[1], l2=L[2];
            float4 q0=R[0], q1=R[1], q2=R[2];
            float ev[9];
            ev[0]=l0.w-q0.w; ev[1]=l1.x-q1.x; ev[2]=l1.y-q1.y;
            ev[3]=l1.z-q1.z; ev[4]=l1.w-q1.w; ev[5]=l2.x-q2.x;
            ev[6]=l2.y-q2.y; ev[7]=l2.z-q2.z; ev[8]=l2.w-q2.w;
            #pragma unroll
            for (int e = 0; e < 3; e++) {
                float ex=ev[3*e], ey=ev[3*e+1], ez=ev[3*e+2];
                float d2 = ex*ex + ey*ey + ez*ez;
                float rs = rsqrtf(d2); float d = d2*rs;
                vA[r][e][0]=ex*rs; vA[r][e][1]=ey*rs; vA[r][e][2]=ez*rs;
                float t1=d-OF1, t2=d-OF2, t3=d-OF3;
                sA[r][e][0]=__expf(COEFF*d*d);
                sA[r][e][1]=__expf(COEFF*t1*t1);
                sA[r][e][2]=__expf(COEFF*t2*t2);
                sA[r][e][3]=__expf(COEFF*t3*t3);
            }
        }

        float cr[2][3];
        u64 s3p[2][4];
        float scal[2];
        u64 accp[2][5];

        // dot12 consumed immediately (G2 loop first) to shorten its live range
        {
            float dot12[2];
            #pragma unroll
            for (int r = 0; r < 2; r++) {
                dot12[r] = vA[r][0][0]*vA[r][1][0] + vA[r][0][1]*vA[r][1][1] + vA[r][0][2]*vA[r][1][2];
                cr[r][0] = vA[r][0][1]*vA[r][1][2] - vA[r][0][2]*vA[r][1][1];
                cr[r][1] = vA[r][0][2]*vA[r][1][0] - vA[r][0][0]*vA[r][1][2];
                cr[r][2] = vA[r][0][0]*vA[r][1][1] - vA[r][0][1]*vA[r][1][0];
                #pragma unroll
                for (int t = 0; t < 4; t++) s3p[r][t] = pack2(sA[r][2][t], sA[r][2][t]);
                #pragma unroll
                for (int k = 0; k < 5; k++) accp[r][k] = 0ull;
                scal[r] = sw[Q0_OFF] * dot12[r];
            }

            // dot12 * (G2 . s3)
            #pragma unroll
            for (int t = 0; t < 4; t++) {
                const float* gb = &sw[G2_OFF + t*12];
                ulonglong2 p0 = *reinterpret_cast<const ulonglong2*>(gb);
                ulonglong2 p1 = *reinterpret_cast<const ulonglong2*>(gb + 4);
                u64 p2 = *reinterpret_cast<const u64*>(gb + 8);
                #pragma unroll
                for (int r = 0; r < 2; r++) {
                    u64 f2 = mul2(pack2(dot12[r], dot12[r]), s3p[r][t]);
                    fma2(accp[r][0], p0.x, f2);
                    fma2(accp[r][1], p0.y, f2);
                    fma2(accp[r][2], p1.x, f2);
                    fma2(accp[r][3], p1.y, f2);
                    fma2(accp[r][4], p2,   f2);
                }
            }
        }

        // Fused trilinear contraction (both big einsums; S never materialized)
        #pragma unroll
        for (int u = 0; u < 4; u++) {
            #pragma unroll
            for (int v = 0; v < 4; v++) {
                float q = sw[Q_OFF + u*4 + v];
                u64 pvp[2];
                #pragma unroll
                for (int r = 0; r < 2; r++) {
                    float pv = sA[r][0][u] * sA[r][1][v];
                    scal[r] += q * pv;
                    pvp[r] = pack2(pv, pv);
                }
                #pragma unroll
                for (int t = 0; t < 4; t++) {
                    const float* wb = &sw[W3_OFF + ((u*4+v)*4 + t)*12];
                    ulonglong2 p0 = *reinterpret_cast<const ulonglong2*>(wb);
                    ulonglong2 p1 = *reinterpret_cast<const ulonglong2*>(wb + 4);
                    u64 p2 = *reinterpret_cast<const u64*>(wb + 8);
                    #pragma unroll
                    for (int r = 0; r < 2; r++) {
                        u64 f2 = mul2(pvp[r], s3p[r][t]);
                        fma2(accp[r][0], p0.x, f2);
                        fma2(accp[r][1], p0.y, f2);
                        fma2(accp[r][2], p1.x, f2);
                        fma2(accp[r][3], p1.y, f2);
                        fma2(accp[r][4], p2,   f2);
                    }
                }
            }
        }

        // Single fused V loop: build V[w] transiently, consume into acc / t2 / wv
        float t2[2][3], wv[2][3];
        #pragma unroll
        for (int r = 0; r < 2; r++) {
            t2[r][0]=scal[r]*vA[r][2][0]; t2[r][1]=scal[r]*vA[r][2][1]; t2[r][2]=scal[r]*vA[r][2][2];
            wv[r][0]=0.f; wv[r][1]=0.f; wv[r][2]=0.f;
        }
        #pragma unroll
        for (int w = 0; w < 5; w++) {
            float a0=sw[A1_OFF+0*5+w], a1=sw[A1_OFF+1*5+w], a2=sw[A1_OFF+2*5+w], a3=sw[A1_OFF+3*5+w];
            float b0=sw[B1_OFF+0*5+w], b1=sw[B1_OFF+1*5+w], b2=sw[B1_OFF+2*5+w], b3=sw[B1_OFF+3*5+w];
            float cw = sw[C5_OFF + w];
            float c0=sw[CM_OFF+w*4+0], c1=sw[CM_OFF+w*4+1], c2=sw[CM_OFF+w*4+2], c3=sw[CM_OFF+w*4+3];
            float ru = sw[R5_OFF + w];
            const float* hb = &sw[H_OFF + w*12];
            ulonglong2 h0 = *reinterpret_cast<const ulonglong2*>(hb);
            ulonglong2 h1 = *reinterpret_cast<const ulonglong2*>(hb + 4);
            u64 h2 = *reinterpret_cast<const u64*>(hb + 8);
            #pragma unroll
            for (int r = 0; r < 2; r++) {
                float aw = a0*sA[r][0][0] + a1*sA[r][0][1] + a2*sA[r][0][2] + a3*sA[r][0][3];
                float bw = b0*sA[r][1][0] + b1*sA[r][1][1] + b2*sA[r][1][2] + b3*sA[r][1][3];
                float Vx = aw*vA[r][1][0] + bw*vA[r][0][0] + cw*cr[r][0];
                float Vy = aw*vA[r][1][1] + bw*vA[r][0][1] + cw*cr[r][1];
                float Vz = aw*vA[r][1][2] + bw*vA[r][0][2] + cw*cr[r][2];
                // H-term
                float vd = Vx*vA[r][2][0] + Vy*vA[r][2][1] + Vz*vA[r][2][2];
                u64 vd2 = pack2(vd, vd);
                fma2(accp[r][0], h0.x, vd2);
                fma2(accp[r][1], h0.y, vd2);
                fma2(accp[r][2], h1.x, vd2);
                fma2(accp[r][3], h1.y, vd2);
                fma2(accp[r][4], h2,   vd2);
                // Cm / r5 terms
                float cu = c0*sA[r][2][0] + c1*sA[r][2][1] + c2*sA[r][2][2] + c3*sA[r][2][3];
                t2[r][0] += cu*Vx; t2[r][1] += cu*Vy; t2[r][2] += cu*Vz;
                wv[r][0] += ru*Vx; wv[r][1] += ru*Vy; wv[r][2] += ru*Vz;
            }
        }

        // final cross into V2
        float v2o[2][3];
        #pragma unroll
        for (int r = 0; r < 2; r++) {
            v2o[r][0] = t2[r][0] + wv[r][1]*vA[r][2][2] - wv[r][2]*vA[r][2][1];
            v2o[r][1] = t2[r][1] + wv[r][2]*vA[r][2][0] - wv[r][0]*vA[r][2][2];
            v2o[r][2] = t2[r][2] + wv[r][0]*vA[r][2][1] - wv[r][1]*vA[r][2][0];
        }

        // stores: 4 concatenated [B,3] regions; unpack accumulators directly
        float2 a0r0 = unpk(accp[0][0]), a1r0 = unpk(accp[0][1]), a2r0 = unpk(accp[0][2]);
        float2 a3r0 = unpk(accp[0][3]), a4r0 = unpk(accp[0][4]);
        float2 a0r1 = unpk(accp[1][0]), a1r1 = unpk(accp[1][1]), a2r1 = unpk(accp[1][2]);
        float2 a3r1 = unpk(accp[1][3]), a4r1 = unpk(accp[1][4]);
        float val0[12] = { a0r0.x,a0r0.y,a1r0.x,a1r0.y,a2r0.x,a2r0.y,a3r0.x,a3r0.y,a4r0.x,
                           v2o[0][0],v2o[0][1],v2o[0][2] };
        float val1[12] = { a0r1.x,a0r1.y,a1r1.x,a1r1.y,a2r1.x,a2r1.y,a3r1.x,a3r1.y,a4r1.x,
                           v2o[1][0],v2o[1][1],v2o[1][2] };

        if (two && ((B & 1) == 0)) {
            #pragma unroll
            for (int g = 0; g < 4; g++) {
                float2* o = reinterpret_cast<float2*>(out + (size_t)(3*g)*B + (size_t)3*r0);
                o[0] = make_float2(val0[3*g+0], val0[3*g+1]);
                o[1] = make_float2(val0[3*g+2], val1[3*g+0]);
                o[2] = make_float2(val1[3*g+1], val1[3*g+2]);
            }
        } else {
            #pragma unroll
            for (int g = 0; g < 4; g++) {
                float* o = out + (size_t)(3*g)*B + (size_t)3*r0;
                o[0]=val0[3*g+0]; o[1]=val0[3*g+1]; o[2]=val0[3*g+2];
                if (two) { o[3]=val1[3*g+0]; o[4]=val1[3*g+1]; o[5]=val1[3*g+2]; }
            }
        }
    }
}

extern "C" void kernel_launch(void* const* d_in, const int* in_sizes, int n_in,
                              void* d_out, int out_size)
{
    const float* lig    = (const float*)d_in[0];
    const float* rec    = (const float*)d_in[1];
    const float* w1_000 = (const float*)d_in[2];
    const float* w1_110 = (const float*)d_in[3];
    const float* w1_011 = (const float*)d_in[4];
    const float* w1_101 = (const float*)d_in[5];
    const float* w1_111 = (const float*)d_in[6];
    const float* w2_000 = (const float*)d_in[7];
    const float* w2_110 = (const float*)d_in[8];
    const float* w2_011 = (const float*)d_in[9];
    const float* w2_101 = (const float*)d_in[10];
    const float* w2_111 = (const float*)d_in[11];

    int B = in_sizes[0] / 12;
    int npairs = (B + 1) / 2;
    int tiles = (npairs + 127) / 128;

    int dev = 0, sms = 148;
    cudaGetDevice(&dev);
    cudaDeviceGetAttribute(&sms, cudaDevAttrMultiProcessorCount, dev);
    int grid = sms * 4;                  // one resident wave (4 blocks/SM)
    if (grid > tiles) grid = tiles;

    dock_kernel<<<grid, 128>>>(
        lig, rec, (float*)d_out, B,
        w1_000, w1_110, w1_011, w1_101, w1_111,
        w2_000, w2_110, w2_011, w2_101, w2_111);
}

// round 16
// speedup vs baseline: 1.0657x; 1.0569x over previous
#include <cuda_runtime.h>
#include <math.h>

// ---------------- composed-weight shared layout (R10 layout) ----------------
//  W3  [64][12] : 0    .. 768   (w padded 9->12, pads ZEROED)
//  G2  [4][12]  : 768  .. 816
//  Q   [4][4]   : 816  .. 832
//  q0           : 832
//  A1  [4][5]   : 836  .. 856
//  B1  [4][5]   : 856  .. 876
//  c5  [5]      : 876  .. 881
//  H   [5][12]  : 884  .. 944   (pads ZEROED)
//  Cm  [5][4]   : 944  .. 964
//  r5  [5]      : 964  .. 969
#define W3_OFF 0
#define G2_OFF 768
#define Q_OFF  816
#define Q0_OFF 832
#define A1_OFF 836
#define B1_OFF 856
#define C5_OFF 876
#define H_OFF  884
#define CM_OFF 944
#define R5_OFF 964
#define PREP_SIZE 976

// ---------------- f32x2 helpers ----------------
typedef unsigned long long u64;

__device__ __forceinline__ u64 pack2(float x, float y) {
    u64 r; asm("mov.b64 %0, {%1, %2};" : "=l"(r) : "f"(x), "f"(y)); return r;
}
__device__ __forceinline__ u64 mul2(u64 a, u64 b) {
    u64 r; asm("mul.rn.f32x2 %0, %1, %2;" : "=l"(r) : "l"(a), "l"(b)); return r;
}
__device__ __forceinline__ void fma2(u64 &d, u64 a, u64 b) {
    asm("fma.rn.f32x2 %0, %1, %2, %0;" : "+l"(d) : "l"(a), "l"(b));
}
__device__ __forceinline__ float2 unpk(u64 v) {
    float2 r; asm("mov.b64 {%0, %1}, %2;" : "=f"(r.x), "=f"(r.y) : "l"(v)); return r;
}

// ---------------- persistent fused kernel: prep once/block + chunked rows ----
// launch_bounds(128, 3): 168-reg cap. R13/R14 proved the (128,4)=128-reg cap
// forces catastrophic spill once the persistent loop adds ~15 regs of state
// on top of the ~120-reg body. 3 blocks/SM costs ~0.5us (R6 vs R10 evidence);
// spill costs 440us. Headroom wins.
__global__ __launch_bounds__(128, 3)
void dock_kernel(const float* __restrict__ lig, const float* __restrict__ rec,
                 float* __restrict__ out, int B,
                 const float* __restrict__ w1_000, const float* __restrict__ w1_110,
                 const float* __restrict__ w1_011, const float* __restrict__ w1_101,
                 const float* __restrict__ w1_111, const float* __restrict__ w2_000,
                 const float* __restrict__ w2_110, const float* __restrict__ w2_011,
                 const float* __restrict__ w2_101, const float* __restrict__ w2_111)
{
    const float C1_000 = 0.24253562503633297f;   // sqrt(1/17)
    const float C1_110 = 0.14002800840280097f;   // sqrt(1/17)/sqrt(3)
    const float C1_011 = 0.3333333333333333f;    // sqrt(3/9)/sqrt(3)
    const float C1_101 = C1_011;
    const float C1_111 = 0.23570226039551587f;   // sqrt(3/9)/sqrt(6)
    const float C2_000 = 0.10846522890932808f;   // sqrt(1/85)
    const float C2_110 = 0.06262242910851495f;   // sqrt(1/85)/sqrt(3)
    const float C2_011 = 0.14907119849998599f;   // sqrt(3/45)/sqrt(3)
    const float C2_101 = C2_011;
    const float C2_111 = 0.10540925533894598f;   // sqrt(3/45)/sqrt(6)

    __shared__ __align__(16) float sw[PREP_SIZE];
    __shared__ float sm1[320];   // w1_000
    __shared__ float sm2[720];   // w2_000
    __shared__ float smv[40];    // [0:20) w1_110, [20:40) w2_011

    const int tid = threadIdx.x;

    // ---- one-time per-block prep (one resident wave; paid once per block) ----
    #pragma unroll
    for (int j = tid; j < PREP_SIZE; j += 128) sw[j] = 0.f;
    #pragma unroll
    for (int j = tid; j < 320; j += 128) sm1[j] = w1_000[j];
    #pragma unroll
    for (int j = tid; j < 720; j += 128) sm2[j] = w2_000[j];
    if (tid < 20)       smv[tid] = w1_110[tid];
    else if (tid < 40)  smv[tid] = w2_011[tid - 20];
    __syncthreads();

    // 629 "20-contraction" outputs split over 128 threads (<=5 iters each)
    for (int j = tid; j < 629; j += 128) {
        if (j < 576) {
            int w = j % 9, t = (j / 9) & 3, uvi = j / 36;
            float s = 0.f;
            #pragma unroll
            for (int m = 0; m < 20; m++) s += sm1[uvi*20 + m] * sm2[(m*4 + t)*9 + w];
            sw[W3_OFF + (uvi*4 + t)*12 + w] = C2_000 * C1_000 * s;
        } else if (j < 612) {
            int k = j - 576, w = k % 9, t = k / 9;
            float s = 0.f;
            #pragma unroll
            for (int m = 0; m < 20; m++) s += smv[m] * sm2[(m*4 + t)*9 + w];
            sw[G2_OFF + t*12 + w] = C2_000 * C1_110 * s;
        } else if (j < 628) {
            int uvi = j - 612;
            float s = 0.f;
            #pragma unroll
            for (int m = 0; m < 20; m++) s += sm1[uvi*20 + m] * smv[20 + m];
            sw[Q_OFF + uvi] = C2_011 * C1_000 * s;
        } else {
            float s = 0.f;
            #pragma unroll
            for (int m = 0; m < 20; m++) s += smv[m] * smv[20 + m];
            sw[Q0_OFF] = C2_011 * C1_110 * s;
        }
    }
    // small tables
    if (tid < 20) sw[A1_OFF + tid] = C1_011 * w1_011[tid];
    if (tid < 20) sw[B1_OFF + tid] = C1_101 * w1_101[tid];
    if (tid < 5)  sw[C5_OFF + tid] = C1_111 * w1_111[tid];
    if (tid < 45) { int u = tid/9, w = tid%9; sw[H_OFF + u*12 + w] = C2_110 * w2_110[tid]; }
    if (tid < 20) sw[CM_OFF + tid] = C2_101 * w2_101[tid];
    if (tid < 5)  sw[R5_OFF + tid] = C2_111 * w2_111[tid];
    __syncthreads();

    // ---- chunked persistent loop over row-pairs (contiguous per block) ----
    const float COEFF = -0.18f;                    // -0.5/(5/3)^2
    const float OF1 = 5.f/3.f, OF2 = 10.f/3.f, OF3 = 5.f;

    const int npairs = (B + 1) >> 1;
    const int chunk  = (npairs + gridDim.x - 1) / gridDim.x;
    const int i_beg  = blockIdx.x * chunk;
    int i_end = i_beg + chunk; if (i_end > npairs) i_end = npairs;

    for (int i = i_beg + tid; i < i_end; i += 128) {
        int r0 = 2 * i;
        bool two = (r0 + 1 < B);

        float sA[2][3][4], vA[2][3][3];
        #pragma unroll
        for (int r = 0; r < 2; r++) {
            int row = (two && r) ? (r0 + 1) : r0;
            const float4* L = reinterpret_cast<const float4*>(lig) + (size_t)row*3;
            const float4* R = reinterpret_cast<const float4*>(rec) + (size_t)row*3;
            float4 l0=L[0], l1=L[1], l2=L[2];
            float4 q0=R[0], q1=R[1], q2=R[2];
            float ev[9];
            ev[0]=l0.w-q0.w; ev[1]=l1.x-q1.x; ev[2]=l1.y-q1.y;
            ev[3]=l1.z-q1.z; ev[4]=l1.w-q1.w; ev[5]=l2.x-q2.x;
            ev[6]=l2.y-q2.y; ev[7]=l2.z-q2.z; ev[8]=l2.w-q2.w;
            #pragma unroll
            for (int e = 0; e < 3; e++) {
                float ex=ev[3*e], ey=ev[3*e+1], ez=ev[3*e+2];
                float d2 = ex*ex + ey*ey + ez*ez;
                float rs = rsqrtf(d2); float d = d2*rs;
                vA[r][e][0]=ex*rs; vA[r][e][1]=ey*rs; vA[r][e][2]=ez*rs;
                float t1=d-OF1, t2=d-OF2, t3=d-OF3;
                sA[r][e][0]=__expf(COEFF*d*d);
                sA[r][e][1]=__expf(COEFF*t1*t1);
                sA[r][e][2]=__expf(COEFF*t2*t2);
                sA[r][e][3]=__expf(COEFF*t3*t3);
            }
        }

        float cr[2][3];
        u64 s3p[2][4];
        float scal[2];
        u64 accp[2][5];

        // dot12 consumed immediately (G2 loop first) to shorten its live range
        {
            float dot12[2];
            #pragma unroll
            for (int r = 0; r < 2; r++) {
                dot12[r] = vA[r][0][0]*vA[r][1][0] + vA[r][0][1]*vA[r][1][1] + vA[r][0][2]*vA[r][1][2];
                cr[r][0] = vA[r][0][1]*vA[r][1][2] - vA[r][0][2]*vA[r][1][1];
                cr[r][1] = vA[r][0][2]*vA[r][1][0] - vA[r][0][0]*vA[r][1][2];
                cr[r][2] = vA[r][0][0]*vA[r][1][1] - vA[r][0][1]*vA[r][1][0];
                #pragma unroll
                for (int t = 0; t < 4; t++) s3p[r][t] = pack2(sA[r][2][t], sA[r][2][t]);
                #pragma unroll
                for (int k = 0; k < 5; k++) accp[r][k] = 0ull;
                scal[r] = sw[Q0_OFF] * dot12[r];
            }

            // dot12 * (G2 . s3)
            #pragma unroll
            for (int t = 0; t < 4; t++) {
                const float* gb = &sw[G2_OFF + t*12];
                ulonglong2 p0 = *reinterpret_cast<const ulonglong2*>(gb);
                ulonglong2 p1 = *reinterpret_cast<const ulonglong2*>(gb + 4);
                u64 p2 = *reinterpret_cast<const u64*>(gb + 8);
                #pragma unroll
                for (int r = 0; r < 2; r++) {
                    u64 f2 = mul2(pack2(dot12[r], dot12[r]), s3p[r][t]);
                    fma2(accp[r][0], p0.x, f2);
                    fma2(accp[r][1], p0.y, f2);
                    fma2(accp[r][2], p1.x, f2);
                    fma2(accp[r][3], p1.y, f2);
                    fma2(accp[r][4], p2,   f2);
                }
            }
        }

        // Fused trilinear contraction (both big einsums; S never materialized)
        #pragma unroll
        for (int u = 0; u < 4; u++) {
            #pragma unroll
            for (int v = 0; v < 4; v++) {
                float q = sw[Q_OFF + u*4 + v];
                u64 pvp[2];
                #pragma unroll
                for (int r = 0; r < 2; r++) {
                    float pv = sA[r][0][u] * sA[r][1][v];
                    scal[r] += q * pv;
                    pvp[r] = pack2(pv, pv);
                }
                #pragma unroll
                for (int t = 0; t < 4; t++) {
                    const float* wb = &sw[W3_OFF + ((u*4+v)*4 + t)*12];
                    ulonglong2 p0 = *reinterpret_cast<const ulonglong2*>(wb);
                    ulonglong2 p1 = *reinterpret_cast<const ulonglong2*>(wb + 4);
                    u64 p2 = *reinterpret_cast<const u64*>(wb + 8);
                    #pragma unroll
                    for (int r = 0; r < 2; r++) {
                        u64 f2 = mul2(pvp[r], s3p[r][t]);
                        fma2(accp[r][0], p0.x, f2);
                        fma2(accp[r][1], p0.y, f2);
                        fma2(accp[r][2], p1.x, f2);
                        fma2(accp[r][3], p1.y, f2);
                        fma2(accp[r][4], p2,   f2);
                    }
                }
            }
        }

        // Single fused V loop: build V[w] transiently, consume into acc / t2 / wv
        float t2[2][3], wv[2][3];
        #pragma unroll
        for (int r = 0; r < 2; r++) {
            t2[r][0]=scal[r]*vA[r][2][0]; t2[r][1]=scal[r]*vA[r][2][1]; t2[r][2]=scal[r]*vA[r][2][2];
            wv[r][0]=0.f; wv[r][1]=0.f; wv[r][2]=0.f;
        }
        #pragma unroll
        for (int w = 0; w < 5; w++) {
            float a0=sw[A1_OFF+0*5+w], a1=sw[A1_OFF+1*5+w], a2=sw[A1_OFF+2*5+w], a3=sw[A1_OFF+3*5+w];
            float b0=sw[B1_OFF+0*5+w], b1=sw[B1_OFF+1*5+w], b2=sw[B1_OFF+2*5+w], b3=sw[B1_OFF+3*5+w];
            float cw = sw[C5_OFF + w];
            float c0=sw[CM_OFF+w*4+0], c1=sw[CM_OFF+w*4+1], c2=sw[CM_OFF+w*4+2], c3=sw[CM_OFF+w*4+3];
            float ru = sw[R5_OFF + w];
            const float* hb = &sw[H_OFF + w*12];
            ulonglong2 h0 = *reinterpret_cast<const ulonglong2*>(hb);
            ulonglong2 h1 = *reinterpret_cast<const ulonglong2*>(hb + 4);
            u64 h2 = *reinterpret_cast<const u64*>(hb + 8);
            #pragma unroll
            for (int r = 0; r < 2; r++) {
                float aw = a0*sA[r][0][0] + a1*sA[r][0][1] + a2*sA[r][0][2] + a3*sA[r][0][3];
                float bw = b0*sA[r][1][0] + b1*sA[r][1][1] + b2*sA[r][1][2] + b3*sA[r][1][3];
                float Vx = aw*vA[r][1][0] + bw*vA[r][0][0] + cw*cr[r][0];
                float Vy = aw*vA[r][1][1] + bw*vA[r][0][1] + cw*cr[r][1];
                float Vz = aw*vA[r][1][2] + bw*vA[r][0][2] + cw*cr[r][2];
                // H-term
                float vd = Vx*vA[r][2][0] + Vy*vA[r][2][1] + Vz*vA[r][2][2];
                u64 vd2 = pack2(vd, vd);
                fma2(accp[r][0], h0.x, vd2);
                fma2(accp[r][1], h0.y, vd2);
                fma2(accp[r][2], h1.x, vd2);
                fma2(accp[r][3], h1.y, vd2);
                fma2(accp[r][4], h2,   vd2);
                // Cm / r5 terms
                float cu = c0*sA[r][2][0] + c1*sA[r][2][1] + c2*sA[r][2][2] + c3*sA[r][2][3];
                t2[r][0] += cu*Vx; t2[r][1] += cu*Vy; t2[r][2] += cu*Vz;
                wv[r][0] += ru*Vx; wv[r][1] += ru*Vy; wv[r][2] += ru*Vz;
            }
        }

        // final cross into V2
        float v2o[2][3];
        #pragma unroll
        for (int r = 0; r < 2; r++) {
            v2o[r][0] = t2[r][0] + wv[r][1]*vA[r][2][2] - wv[r][2]*vA[r][2][1];
            v2o[r][1] = t2[r][1] + wv[r][2]*vA[r][2][0] - wv[r][0]*vA[r][2][2];
            v2o[r][2] = t2[r][2] + wv[r][0]*vA[r][2][1] - wv[r][1]*vA[r][2][0];
        }

        // stores: 4 concatenated [B,3] regions; unpack accumulators directly
        float2 a0r0 = unpk(accp[0][0]), a1r0 = unpk(accp[0][1]), a2r0 = unpk(accp[0][2]);
        float2 a3r0 = unpk(accp[0][3]), a4r0 = unpk(accp[0][4]);
        float2 a0r1 = unpk(accp[1][0]), a1r1 = unpk(accp[1][1]), a2r1 = unpk(accp[1][2]);
        float2 a3r1 = unpk(accp[1][3]), a4r1 = unpk(accp[1][4]);
        float val0[12] = { a0r0.x,a0r0.y,a1r0.x,a1r0.y,a2r0.x,a2r0.y,a3r0.x,a3r0.y,a4r0.x,
                           v2o[0][0],v2o[0][1],v2o[0][2] };
        float val1[12] = { a0r1.x,a0r1.y,a1r1.x,a1r1.y,a2r1.x,a2r1.y,a3r1.x,a3r1.y,a4r1.x,
                           v2o[1][0],v2o[1][1],v2o[1][2] };

        if (two && ((B & 1) == 0)) {
            #pragma unroll
            for (int g = 0; g < 4; g++) {
                float2* o = reinterpret_cast<float2*>(out + (size_t)(3*g)*B + (size_t)3*r0);
                o[0] = make_float2(val0[3*g+0], val0[3*g+1]);
                o[1] = make_float2(val0[3*g+2], val1[3*g+0]);
                o[2] = make_float2(val1[3*g+1], val1[3*g+2]);
            }
        } else {
            #pragma unroll
            for (int g = 0; g < 4; g++) {
                float* o = out + (size_t)(3*g)*B + (size_t)3*r0;
                o[0]=val0[3*g+0]; o[1]=val0[3*g+1]; o[2]=val0[3*g+2];
                if (two) { o[3]=val1[3*g+0]; o[4]=val1[3*g+1]; o[5]=val1[3*g+2]; }
            }
        }
    }
}

extern "C" void kernel_launch(void* const* d_in, const int* in_sizes, int n_in,
                              void* d_out, int out_size)
{
    const float* lig    = (const float*)d_in[0];
    const float* rec    = (const float*)d_in[1];
    const float* w1_000 = (const float*)d_in[2];
    const float* w1_110 = (const float*)d_in[3];
    const float* w1_011 = (const float*)d_in[4];
    const float* w1_101 = (const float*)d_in[5];
    const float* w1_111 = (const float*)d_in[6];
    const float* w2_000 = (const float*)d_in[7];
    const float* w2_110 = (const float*)d_in[8];
    const float* w2_011 = (const float*)d_in[9];
    const float* w2_101 = (const float*)d_in[10];
    const float* w2_111 = (const float*)d_in[11];

    int B = in_sizes[0] / 12;
    int npairs = (B + 1) / 2;
    int tiles = (npairs + 127) / 128;

    int dev = 0, sms = 148;
    cudaGetDevice(&dev);
    cudaDeviceGetAttribute(&sms, cudaDevAttrMultiProcessorCount, dev);
    int grid = sms * 3;                  // one resident wave (3 blocks/SM @ 168-reg cap)
    if (grid > tiles) grid = tiles;

    dock_kernel<<<grid, 128>>>(
        lig, rec, (float*)d_out, B,
        w1_000, w1_110, w1_011, w1_101, w1_111,
        w2_000, w2_110, w2_011, w2_101, w2_111);
}

// round 17
// speedup vs baseline: 8.8904x; 8.3419x over previous
#include <cuda_runtime.h>
#include <math.h>

// ---------------- precomputed composed-weight scratch (R10 layout) ----------------
//  W3  [64][12] : 0    .. 768   (w padded 9->12, pads ZEROED)
//  G2  [4][12]  : 768  .. 816
//  Q   [4][4]   : 816  .. 832
//  q0           : 832
//  A1  [4][5]   : 836  .. 856
//  B1  [4][5]   : 856  .. 876
//  c5  [5]      : 876  .. 881
//  H   [5][12]  : 884  .. 944   (pads ZEROED)
//  Cm  [5][4]   : 944  .. 964
//  r5  [5]      : 964  .. 969
#define W3_OFF 0
#define G2_OFF 768
#define Q_OFF  816
#define Q0_OFF 832
#define A1_OFF 836
#define B1_OFF 856
#define C5_OFF 876
#define H_OFF  884
#define CM_OFF 944
#define R5_OFF 964
#define PREP_SIZE 976

__device__ float g_prep[PREP_SIZE];

__global__ void prep_kernel(const float* __restrict__ w1_000, const float* __restrict__ w1_110,
                            const float* __restrict__ w1_011, const float* __restrict__ w1_101,
                            const float* __restrict__ w1_111, const float* __restrict__ w2_000,
                            const float* __restrict__ w2_110, const float* __restrict__ w2_011,
                            const float* __restrict__ w2_101, const float* __restrict__ w2_111)
{
    const float C1_000 = 0.24253562503633297f;   // sqrt(1/17)
    const float C1_110 = 0.14002800840280097f;   // sqrt(1/17)/sqrt(3)
    const float C1_011 = 0.3333333333333333f;    // sqrt(3/9)/sqrt(3)
    const float C1_101 = C1_011;
    const float C1_111 = 0.23570226039551587f;   // sqrt(3/9)/sqrt(6)
    const float C2_000 = 0.10846522890932808f;   // sqrt(1/85)
    const float C2_110 = 0.06262242910851495f;   // sqrt(1/85)/sqrt(3)
    const float C2_011 = 0.14907119849998599f;   // sqrt(3/45)/sqrt(3)
    const float C2_101 = C2_011;
    const float C2_111 = 0.10540925533894598f;   // sqrt(3/45)/sqrt(6)

    __shared__ float sm1[320];   // w1_000
    __shared__ float sm2[720];   // w2_000
    __shared__ float sm110[20];  // w1_110
    __shared__ float sm011[20];  // w2_011

    int tid = threadIdx.x;   // 576 threads

    // stage all weights used in 20-contractions into smem (coalesced, high MLP)
    if (tid < 320) sm1[tid] = w1_000[tid];
    for (int j = tid; j < 720; j += 576) sm2[j] = w2_000[j];
    if (tid < 20) { sm110[tid] = w1_110[tid]; sm011[tid] = w2_011[tid]; }
    // zero padded table (padding lanes must be exactly 0)
    for (int j = tid; j < PREP_SIZE; j += 576) g_prep[j] = 0.f;
    __syncthreads();

    if (tid < 576) {
        int w = tid % 9, t = (tid/9) % 4, v = (tid/36) % 4, u = tid/144;
        float s = 0.f;
        #pragma unroll
        for (int m = 0; m < 20; m++)
            s += sm1[(u*4+v)*20 + m] * sm2[(m*4+t)*9 + w];
        g_prep[W3_OFF + ((u*4+v)*4 + t)*12 + w] = C2_000 * C1_000 * s;
    }
    if (tid < 36) {
        int w = tid % 9, t = tid/9;
        float s = 0.f;
        #pragma unroll
        for (int m = 0; m < 20; m++) s += sm110[m] * sm2[(m*4+t)*9 + w];
        g_prep[G2_OFF + t*12 + w] = C2_000 * C1_110 * s;
    }
    if (tid < 16) {
        float s = 0.f;
        #pragma unroll
        for (int m = 0; m < 20; m++) s += sm1[tid*20 + m] * sm011[m];
        g_prep[Q_OFF + tid] = C2_011 * C1_000 * s;
    }
    if (tid == 0) {
        float s = 0.f;
        #pragma unroll
        for (int m = 0; m < 20; m++) s += sm110[m] * sm011[m];
        g_prep[Q0_OFF] = C2_011 * C1_110 * s;
    }
    if (tid < 20) g_prep[A1_OFF + tid] = C1_011 * w1_011[tid];
    if (tid < 20) g_prep[B1_OFF + tid] = C1_101 * w1_101[tid];
    if (tid < 5)  g_prep[C5_OFF + tid] = C1_111 * w1_111[tid];
    if (tid < 45) { int u = tid/9, w = tid%9; g_prep[H_OFF + u*12 + w] = C2_110 * w2_110[tid]; }
    if (tid < 20) g_prep[CM_OFF + tid] = C2_101 * w2_101[tid];
    if (tid < 5)  g_prep[R5_OFF + tid] = C2_111 * w2_111[tid];

#if __CUDA_ARCH__ >= 900
    // PDL: all g_prep writes above are done in this thread; allow the dependent
    // dock_kernel grid to begin (its cudaGridDependencySynchronize orders reads).
    cudaTriggerProgrammaticLaunchCompletion();
#endif
}

// ---------------- f32x2 helpers ----------------
typedef unsigned long long u64;

__device__ __forceinline__ u64 pack2(float x, float y) {
    u64 r; asm("mov.b64 %0, {%1, %2};" : "=l"(r) : "f"(x), "f"(y)); return r;
}
__device__ __forceinline__ u64 mul2(u64 a, u64 b) {
    u64 r; asm("mul.rn.f32x2 %0, %1, %2;" : "=l"(r) : "l"(a), "l"(b)); return r;
}
__device__ __forceinline__ void fma2(u64 &d, u64 a, u64 b) {
    asm("fma.rn.f32x2 %0, %1, %2, %0;" : "+l"(d) : "l"(a), "l"(b));
}
__device__ __forceinline__ float2 unpk(u64 v) {
    float2 r; asm("mov.b64 {%0, %1}, %2;" : "=f"(r.x), "=f"(r.y) : "l"(v)); return r;
}

// ---------------- main kernel: 2 rows per thread, 4 blocks/SM (R10 body) ----------------
__global__ __launch_bounds__(128, 4)
void dock_kernel(const float* __restrict__ lig, const float* __restrict__ rec,
                 float* __restrict__ out, int B)
{
#if __CUDA_ARCH__ >= 900
    // PDL: this grid may have launched before prep_kernel finished; wait for it
    // before touching g_prep. Scheduling/ramp-up latency is overlapped with prep.
    cudaGridDependencySynchronize();
#endif

    __shared__ __align__(16) float sw[PREP_SIZE];
    for (int j = threadIdx.x; j < PREP_SIZE; j += 128) sw[j] = g_prep[j];
    __syncthreads();

    int i = blockIdx.x * 128 + threadIdx.x;
    int r0 = 2 * i;
    if (r0 >= B) return;
    bool two = (r0 + 1 < B);

    const float COEFF = -0.18f;                    // -0.5/(5/3)^2
    const float OF1 = 5.f/3.f, OF2 = 10.f/3.f, OF3 = 5.f;

    float sA[2][3][4], vA[2][3][3];
    #pragma unroll
    for (int r = 0; r < 2; r++) {
        int row = (two && r) ? (r0 + 1) : r0;
        const float4* L = reinterpret_cast<const float4*>(lig) + (size_t)row*3;
        const float4* R = reinterpret_cast<const float4*>(rec) + (size_t)row*3;
        float4 l0=L[0], l1=L[1], l2=L[2];
        float4 q0=R[0], q1=R[1], q2=R[2];
        float ev[9];
        ev[0]=l0.w-q0.w; ev[1]=l1.x-q1.x; ev[2]=l1.y-q1.y;
        ev[3]=l1.z-q1.z; ev[4]=l1.w-q1.w; ev[5]=l2.x-q2.x;
        ev[6]=l2.y-q2.y; ev[7]=l2.z-q2.z; ev[8]=l2.w-q2.w;
        #pragma unroll
        for (int e = 0; e < 3; e++) {
            float ex=ev[3*e], ey=ev[3*e+1], ez=ev[3*e+2];
            float d2 = ex*ex + ey*ey + ez*ez;
            float rs = rsqrtf(d2); float d = d2*rs;
            vA[r][e][0]=ex*rs; vA[r][e][1]=ey*rs; vA[r][e][2]=ez*rs;
            float t1=d-OF1, t2=d-OF2, t3=d-OF3;
            sA[r][e][0]=__expf(COEFF*d*d);
            sA[r][e][1]=__expf(COEFF*t1*t1);
            sA[r][e][2]=__expf(COEFF*t2*t2);
            sA[r][e][3]=__expf(COEFF*t3*t3);
        }
    }

    float dot12[2], cr[2][3];
    u64 s3p[2][4];
    #pragma unroll
    for (int r = 0; r < 2; r++) {
        dot12[r] = vA[r][0][0]*vA[r][1][0] + vA[r][0][1]*vA[r][1][1] + vA[r][0][2]*vA[r][1][2];
        cr[r][0] = vA[r][0][1]*vA[r][1][2] - vA[r][0][2]*vA[r][1][1];
        cr[r][1] = vA[r][0][2]*vA[r][1][0] - vA[r][0][0]*vA[r][1][2];
        cr[r][2] = vA[r][0][0]*vA[r][1][1] - vA[r][0][1]*vA[r][1][0];
        #pragma unroll
        for (int t = 0; t < 4; t++) s3p[r][t] = pack2(sA[r][2][t], sA[r][2][t]);
    }

    u64 accp[2][5];
    #pragma unroll
    for (int r = 0; r < 2; r++)
        #pragma unroll
        for (int k = 0; k < 5; k++) accp[r][k] = 0ull;

    // scal folded into trilinear (u,v) loop
    float scal[2];
    scal[0] = sw[Q0_OFF] * dot12[0];
    scal[1] = sw[Q0_OFF] * dot12[1];

    // Fused trilinear contraction (both big einsums; S never materialized)
    #pragma unroll
    for (int u = 0; u < 4; u++) {
        #pragma unroll
        for (int v = 0; v < 4; v++) {
            float q = sw[Q_OFF + u*4 + v];
            u64 pvp[2];
            #pragma unroll
            for (int r = 0; r < 2; r++) {
                float pv = sA[r][0][u] * sA[r][1][v];
                scal[r] += q * pv;
                pvp[r] = pack2(pv, pv);
            }
            #pragma unroll
            for (int t = 0; t < 4; t++) {
                const float* wb = &sw[W3_OFF + ((u*4+v)*4 + t)*12];
                ulonglong2 p0 = *reinterpret_cast<const ulonglong2*>(wb);
                ulonglong2 p1 = *reinterpret_cast<const ulonglong2*>(wb + 4);
                u64 p2 = *reinterpret_cast<const u64*>(wb + 8);
                #pragma unroll
                for (int r = 0; r < 2; r++) {
                    u64 f2 = mul2(pvp[r], s3p[r][t]);
                    fma2(accp[r][0], p0.x, f2);
                    fma2(accp[r][1], p0.y, f2);
                    fma2(accp[r][2], p1.x, f2);
                    fma2(accp[r][3], p1.y, f2);
                    fma2(accp[r][4], p2,   f2);
                }
            }
        }
    }

    // dot12 * (G2 . s3)
    #pragma unroll
    for (int t = 0; t < 4; t++) {
        const float* gb = &sw[G2_OFF + t*12];
        ulonglong2 p0 = *reinterpret_cast<const ulonglong2*>(gb);
        ulonglong2 p1 = *reinterpret_cast<const ulonglong2*>(gb + 4);
        u64 p2 = *reinterpret_cast<const u64*>(gb + 8);
        #pragma unroll
        for (int r = 0; r < 2; r++) {
            u64 f2 = mul2(pack2(dot12[r], dot12[r]), s3p[r][t]);
            fma2(accp[r][0], p0.x, f2);
            fma2(accp[r][1], p0.y, f2);
            fma2(accp[r][2], p1.x, f2);
            fma2(accp[r][3], p1.y, f2);
            fma2(accp[r][4], p2,   f2);
        }
    }

    // Single fused V loop: build V[w] transiently, consume into acc / t2 / wv
    float t2[2][3], wv[2][3];
    #pragma unroll
    for (int r = 0; r < 2; r++) {
        t2[r][0]=scal[r]*vA[r][2][0]; t2[r][1]=scal[r]*vA[r][2][1]; t2[r][2]=scal[r]*vA[r][2][2];
        wv[r][0]=0.f; wv[r][1]=0.f; wv[r][2]=0.f;
    }
    #pragma unroll
    for (int w = 0; w < 5; w++) {
        float a0=sw[A1_OFF+0*5+w], a1=sw[A1_OFF+1*5+w], a2=sw[A1_OFF+2*5+w], a3=sw[A1_OFF+3*5+w];
        float b0=sw[B1_OFF+0*5+w], b1=sw[B1_OFF+1*5+w], b2=sw[B1_OFF+2*5+w], b3=sw[B1_OFF+3*5+w];
        float cw = sw[C5_OFF + w];
        float c0=sw[CM_OFF+w*4+0], c1=sw[CM_OFF+w*4+1], c2=sw[CM_OFF+w*4+2], c3=sw[CM_OFF+w*4+3];
        float ru = sw[R5_OFF + w];
        const float* hb = &sw[H_OFF + w*12];
        ulonglong2 h0 = *reinterpret_cast<const ulonglong2*>(hb);
        ulonglong2 h1 = *reinterpret_cast<const ulonglong2*>(hb + 4);
        u64 h2 = *reinterpret_cast<const u64*>(hb + 8);
        #pragma unroll
        for (int r = 0; r < 2; r++) {
            float aw = a0*sA[r][0][0] + a1*sA[r][0][1] + a2*sA[r][0][2] + a3*sA[r][0][3];
            float bw = b0*sA[r][1][0] + b1*sA[r][1][1] + b2*sA[r][1][2] + b3*sA[r][1][3];
            float Vx = aw*vA[r][1][0] + bw*vA[r][0][0] + cw*cr[r][0];
            float Vy = aw*vA[r][1][1] + bw*vA[r][0][1] + cw*cr[r][1];
            float Vz = aw*vA[r][1][2] + bw*vA[r][0][2] + cw*cr[r][2];
            // H-term
            float vd = Vx*vA[r][2][0] + Vy*vA[r][2][1] + Vz*vA[r][2][2];
            u64 vd2 = pack2(vd, vd);
            fma2(accp[r][0], h0.x, vd2);
            fma2(accp[r][1], h0.y, vd2);
            fma2(accp[r][2], h1.x, vd2);
            fma2(accp[r][3], h1.y, vd2);
            fma2(accp[r][4], h2,   vd2);
            // Cm / r5 terms
            float cu = c0*sA[r][2][0] + c1*sA[r][2][1] + c2*sA[r][2][2] + c3*sA[r][2][3];
            t2[r][0] += cu*Vx; t2[r][1] += cu*Vy; t2[r][2] += cu*Vz;
            wv[r][0] += ru*Vx; wv[r][1] += ru*Vy; wv[r][2] += ru*Vz;
        }
    }

    // final cross into V2
    float v2o[2][3];
    #pragma unroll
    for (int r = 0; r < 2; r++) {
        v2o[r][0] = t2[r][0] + wv[r][1]*vA[r][2][2] - wv[r][2]*vA[r][2][1];
        v2o[r][1] = t2[r][1] + wv[r][2]*vA[r][2][0] - wv[r][0]*vA[r][2][2];
        v2o[r][2] = t2[r][2] + wv[r][0]*vA[r][2][1] - wv[r][1]*vA[r][2][0];
    }

    // stores: 4 concatenated [B,3] regions; unpack accumulators directly
    float2 a0r0 = unpk(accp[0][0]), a1r0 = unpk(accp[0][1]), a2r0 = unpk(accp[0][2]);
    float2 a3r0 = unpk(accp[0][3]), a4r0 = unpk(accp[0][4]);
    float2 a0r1 = unpk(accp[1][0]), a1r1 = unpk(accp[1][1]), a2r1 = unpk(accp[1][2]);
    float2 a3r1 = unpk(accp[1][3]), a4r1 = unpk(accp[1][4]);
    float val0[12] = { a0r0.x,a0r0.y,a1r0.x,a1r0.y,a2r0.x,a2r0.y,a3r0.x,a3r0.y,a4r0.x,
                       v2o[0][0],v2o[0][1],v2o[0][2] };
    float val1[12] = { a0r1.x,a0r1.y,a1r1.x,a1r1.y,a2r1.x,a2r1.y,a3r1.x,a3r1.y,a4r1.x,
                       v2o[1][0],v2o[1][1],v2o[1][2] };

    if (two && ((B & 1) == 0)) {
        #pragma unroll
        for (int g = 0; g < 4; g++) {
            float2* o = reinterpret_cast<float2*>(out + (size_t)(3*g)*B + (size_t)3*r0);
            o[0] = make_float2(val0[3*g+0], val0[3*g+1]);
            o[1] = make_float2(val0[3*g+2], val1[3*g+0]);
            o[2] = make_float2(val1[3*g+1], val1[3*g+2]);
        }
    } else {
        #pragma unroll
        for (int g = 0; g < 4; g++) {
            float* o = out + (size_t)(3*g)*B + (size_t)3*r0;
            o[0]=val0[3*g+0]; o[1]=val0[3*g+1]; o[2]=val0[3*g+2];
            if (two) { o[3]=val1[3*g+0]; o[4]=val1[3*g+1]; o[5]=val1[3*g+2]; }
        }
    }
}

extern "C" void kernel_launch(void* const* d_in, const int* in_sizes, int n_in,
                              void* d_out, int out_size)
{
    const float* lig    = (const float*)d_in[0];
    const float* rec    = (const float*)d_in[1];
    const float* w1_000 = (const float*)d_in[2];
    const float* w1_110 = (const float*)d_in[3];
    const float* w1_011 = (const float*)d_in[4];
    const float* w1_101 = (const float*)d_in[5];
    const float* w1_111 = (const float*)d_in[6];
    const float* w2_000 = (const float*)d_in[7];
    const float* w2_110 = (const float*)d_in[8];
    const float* w2_011 = (const float*)d_in[9];
    const float* w2_101 = (const float*)d_in[10];
    const float* w2_111 = (const float*)d_in[11];

    int B = in_sizes[0] / 12;
    int nthreads = (B + 1) / 2;
    unsigned int grid = (unsigned int)((nthreads + 127) / 128);

    prep_kernel<<<1, 576>>>(w1_000, w1_110, w1_011, w1_101, w1_111,
                            w2_000, w2_110, w2_011, w2_101, w2_111);

    // Launch dock with PDL so its scheduling overlaps prep's execution;
    // the device-side cudaGridDependencySynchronize orders the g_prep reads.
    cudaLaunchConfig_t cfg = {};
    cfg.gridDim  = dim3(grid, 1, 1);
    cfg.blockDim = dim3(128, 1, 1);
    cfg.dynamicSmemBytes = 0;
    cudaLaunchAttribute attrs[1];
    attrs[0].id = cudaLaunchAttributeProgrammaticStreamSerialization;
    attrs[0].val.programmaticStreamSerializationAllowed = 1;
    cfg.attrs = attrs;
    cfg.numAttrs = 1;

    cudaError_t err = cudaLaunchKernelEx(&cfg, dock_kernel,
                                         lig, rec, (float*)d_out, B);
    if (err != cudaSuccess) {
        // Fallback: plain launch (no PDL) — still correct.
        dock_kernel<<<grid, 128>>>(lig, rec, (float*)d_out, B);
    }
}